// round 7
// baseline (speedup 1.0000x reference)
#include <cuda_runtime.h>
#include <cstdint>

// ---------------------------------------------------------------------------
// Problem constants
// ---------------------------------------------------------------------------
#define T_STEPS 2048
#define BATCH   64
#define INSZ    512
#define HID     256
#define G4      1024      // 4*HID
#define OUTSZ   128
#define MROWS   (T_STEPS * BATCH)   // 131072

// Scratch (device globals: allocation-free per harness rules)
__device__ float g_Xp[(size_t)MROWS * G4];   // input projection + biases
__device__ float g_hs[(size_t)MROWS * HID];  // hidden states

// ---------------------------------------------------------------------------
// Packed fp32x2 FMA (SASS FFMA2) — used in the recurrence.
// ---------------------------------------------------------------------------
__device__ __forceinline__ void ffma2(float2& d, const float2& a, const float2& b)
{
    asm("fma.rn.f32x2 %0, %1, %2, %0;"
        : "+l"(reinterpret_cast<unsigned long long&>(d))
        : "l"(reinterpret_cast<const unsigned long long&>(a)),
          "l"(reinterpret_cast<const unsigned long long&>(b)));
}

// ---------------------------------------------------------------------------
// 3xTF32 tensor-core GEMM (NT) — unchanged from round 4.
// ---------------------------------------------------------------------------
__device__ __forceinline__ float2 split_tf32(float x)
{
    uint32_t h;
    asm("cvt.rna.tf32.f32 %0, %1;" : "=r"(h) : "f"(x));
    float hf = __uint_as_float(h);
    float lo = x - hf;
    uint32_t l;
    asm("cvt.rna.tf32.f32 %0, %1;" : "=r"(l) : "f"(lo));
    return make_float2(hf, __uint_as_float(l));
}

#define MMA_TF32(d, a0, a1, a2, a3, b0, b1)                                   \
    asm("mma.sync.aligned.m16n8k8.row.col.f32.tf32.tf32.f32 "                  \
        "{%0,%1,%2,%3},{%4,%5,%6,%7},{%8,%9},{%0,%1,%2,%3};"                   \
        : "+f"((d)[0]), "+f"((d)[1]), "+f"((d)[2]), "+f"((d)[3])               \
        : "r"(a0), "r"(a1), "r"(a2), "r"(a3), "r"(b0), "r"(b1))

#define SPAD 18   // float2 row stride (16 K + 2 pad)

__global__ void __launch_bounds__(256)
tgemm128(const float* __restrict__ A, const float* __restrict__ Bm,
         const float* __restrict__ bias1, const float* __restrict__ bias2,
         float* __restrict__ C, int K, int N)
{
    __shared__ float2 As[128][SPAD];   // (hi, lo) pairs
    __shared__ float2 Bs[128][SPAD];

    const int tid  = threadIdx.x;
    const int lane = tid & 31;
    const int warp = tid >> 5;
    const int wm = warp & 1;
    const int wn = warp >> 1;
    const int g  = lane >> 2;
    const int t  = lane & 3;

    const size_t m0 = (size_t)blockIdx.x * 128;
    const int    n0 = blockIdx.y * 128;

    const int lrow = tid >> 1;
    const int lc   = (tid & 1) * 8;
    const float* Ag = A  + (m0 + lrow) * (size_t)K + lc;
    const float* Bg = Bm + (size_t)(n0 + lrow) * K + lc;

    float acc[4][4][4];
#pragma unroll
    for (int i = 0; i < 4; ++i)
#pragma unroll
        for (int j = 0; j < 4; ++j)
#pragma unroll
            for (int q = 0; q < 4; ++q) acc[i][j][q] = 0.f;

    for (int k0 = 0; k0 < K; k0 += 16) {
        float4 av0 = *(const float4*)(Ag + k0);
        float4 av1 = *(const float4*)(Ag + k0 + 4);
        float4 bv0 = *(const float4*)(Bg + k0);
        float4 bv1 = *(const float4*)(Bg + k0 + 4);
        __syncthreads();
        As[lrow][lc + 0] = split_tf32(av0.x);
        As[lrow][lc + 1] = split_tf32(av0.y);
        As[lrow][lc + 2] = split_tf32(av0.z);
        As[lrow][lc + 3] = split_tf32(av0.w);
        As[lrow][lc + 4] = split_tf32(av1.x);
        As[lrow][lc + 5] = split_tf32(av1.y);
        As[lrow][lc + 6] = split_tf32(av1.z);
        As[lrow][lc + 7] = split_tf32(av1.w);
        Bs[lrow][lc + 0] = split_tf32(bv0.x);
        Bs[lrow][lc + 1] = split_tf32(bv0.y);
        Bs[lrow][lc + 2] = split_tf32(bv0.z);
        Bs[lrow][lc + 3] = split_tf32(bv0.w);
        Bs[lrow][lc + 4] = split_tf32(bv1.x);
        Bs[lrow][lc + 5] = split_tf32(bv1.y);
        Bs[lrow][lc + 6] = split_tf32(bv1.z);
        Bs[lrow][lc + 7] = split_tf32(bv1.w);
        __syncthreads();

#pragma unroll
        for (int ks = 0; ks < 2; ++ks) {
            const int kb = ks * 8;
            uint32_t ah[4][4], al[4][4], bh[4][2], bl[4][2];
#pragma unroll
            for (int i = 0; i < 4; ++i) {
                int row = wm * 64 + i * 16 + g;
                float2 v00 = As[row][kb + t];
                float2 v10 = As[row + 8][kb + t];
                float2 v01 = As[row][kb + t + 4];
                float2 v11 = As[row + 8][kb + t + 4];
                ah[i][0] = __float_as_uint(v00.x);
                ah[i][1] = __float_as_uint(v10.x);
                ah[i][2] = __float_as_uint(v01.x);
                ah[i][3] = __float_as_uint(v11.x);
                al[i][0] = __float_as_uint(v00.y);
                al[i][1] = __float_as_uint(v10.y);
                al[i][2] = __float_as_uint(v01.y);
                al[i][3] = __float_as_uint(v11.y);
            }
#pragma unroll
            for (int j = 0; j < 4; ++j) {
                int n = wn * 32 + j * 8 + g;
                float2 w0 = Bs[n][kb + t];
                float2 w1 = Bs[n][kb + t + 4];
                bh[j][0] = __float_as_uint(w0.x);
                bh[j][1] = __float_as_uint(w1.x);
                bl[j][0] = __float_as_uint(w0.y);
                bl[j][1] = __float_as_uint(w1.y);
            }
#pragma unroll
            for (int i = 0; i < 4; ++i)
#pragma unroll
                for (int j = 0; j < 4; ++j) {
                    MMA_TF32(acc[i][j], ah[i][0], ah[i][1], ah[i][2], ah[i][3],
                             bh[j][0], bh[j][1]);
                    MMA_TF32(acc[i][j], ah[i][0], ah[i][1], ah[i][2], ah[i][3],
                             bl[j][0], bl[j][1]);
                    MMA_TF32(acc[i][j], al[i][0], al[i][1], al[i][2], al[i][3],
                             bh[j][0], bh[j][1]);
                }
        }
    }

#pragma unroll
    for (int j = 0; j < 4; ++j) {
        int col = n0 + wn * 32 + j * 8 + 2 * t;
        float b0 = bias1[col], b1 = bias1[col + 1];
        if (bias2) { b0 += bias2[col]; b1 += bias2[col + 1]; }
#pragma unroll
        for (int i = 0; i < 4; ++i) {
            size_t row = m0 + wm * 64 + i * 16 + g;
            *(float2*)(C + row * N + col) =
                make_float2(acc[i][j][0] + b0, acc[i][j][1] + b1);
            *(float2*)(C + (row + 8) * N + col) =
                make_float2(acc[i][j][2] + b0, acc[i][j][3] + b1);
        }
    }
}

// ---------------------------------------------------------------------------
// mbarrier helpers
// ---------------------------------------------------------------------------
__device__ __forceinline__ void mbar_init(uint32_t addr, uint32_t count)
{
    asm volatile("mbarrier.init.shared.b64 [%0], %1;" :: "r"(addr), "r"(count)
                 : "memory");
}
__device__ __forceinline__ void mbar_expect_tx(uint32_t addr, uint32_t bytes)
{
    asm volatile("mbarrier.arrive.expect_tx.shared.b64 _, [%0], %1;"
                 :: "r"(addr), "r"(bytes) : "memory");
}
__device__ __forceinline__ void mbar_wait(uint32_t addr, uint32_t parity)
{
    asm volatile(
        "{\n\t"
        ".reg .pred P;\n\t"
        "LW%=:\n\t"
        "mbarrier.try_wait.parity.acquire.cta.shared::cta.b64 P, [%0], %1;\n\t"
        "@P bra LD%=;\n\t"
        "bra LW%=;\n\t"
        "LD%=:\n\t"
        "}"
        :: "r"(addr), "r"(parity) : "memory");
}

// ---------------------------------------------------------------------------
// LSTM recurrence v5: per-(slot,rank) mbarriers + COALESCED st.async.v4
// scatter (256 x 16B messages per CTA per step instead of 1024 x 4B).
//
// 16 clusters x 8 CTAs x 256 threads. Cluster cl owns batches [cl*4, cl*4+4).
// CTA rank r owns h outputs j = r*32 + jj (all 4 gates).
// Warp w consumes ONLY rank w's 512B h-block each step -> waits only
// mbar[slot][w] (cross-CTA skew overlaps with the dot phase).
//
// h ring: hsm[slot=3][rank=8][batch=4][32]. After gates, reducers stage h in
// hstage; after a second __syncthreads ALL 256 threads push one float4 each:
// dst = tid>>5, q = tid&31 -> peer dst's hsm[ws][r][q*4..], completing
// mbar[ws][r] on that peer (32 msgs x 16B = 512B per barrier per phase).
// ---------------------------------------------------------------------------
__global__ void __launch_bounds__(256, 1)
lstm_rec_kernel(const float* __restrict__ Whh,
                const float* __restrict__ Xp,
                float* __restrict__ hs)
{
    __shared__ float  hsm[3 * 1024];          // [slot][rank][batch][32]
    __shared__ float4 part[8][4][32];         // [warp][batch][jj] = 4 gates
    __shared__ float  hstage[128];            // [batch*32 + jj]
    __shared__ __align__(8) unsigned long long mbar[24];  // [slot][rank]

    const int tid  = threadIdx.x;
    const int lane = tid & 31;
    const int w    = tid >> 5;

    unsigned r;
    asm("mov.u32 %0, %%cluster_ctarank;" : "=r"(r));
    const int cl = blockIdx.x >> 3;

    const uint32_t hsm_s = (uint32_t)__cvta_generic_to_shared(hsm);
    const uint32_t mb_s  = (uint32_t)__cvta_generic_to_shared(mbar);

    // This thread's fixed scatter target: peer (tid>>5), quad (tid&31).
    const int sdst = tid >> 5;
    const int sq   = tid & 31;
    uint32_t sc_data_base, sc_mbar_base;
    asm("mapa.shared::cluster.u32 %0, %1, %2;"
        : "=r"(sc_data_base) : "r"(hsm_s + r * 512u + (uint32_t)sq * 16u),
          "r"(sdst));
    asm("mapa.shared::cluster.u32 %0, %1, %2;"
        : "=r"(sc_mbar_base) : "r"(mb_s + r * 8u), "r"(sdst));

    // Weights: gate rr, output jj=lane, k-chunk w*32..w*32+31 (64 f32x2 regs).
    float2 wreg[4][16];
#pragma unroll
    for (int rr = 0; rr < 4; ++rr) {
        int grow = rr * 256 + (int)r * 32 + lane;
        const float2* wp = (const float2*)(Whh + (size_t)grow * 256 + w * 32);
#pragma unroll
        for (int k2 = 0; k2 < 16; ++k2) wreg[rr][k2] = wp[k2];
    }
    for (int i = tid; i < 3 * 1024; i += 256) hsm[i] = 0.f;  // slot0 = h0 = 0
    if (tid < 24) mbar_init(mb_s + tid * 8, 1);
    __syncthreads();
    if (tid < 24) mbar_expect_tx(mb_s + tid * 8, 512u);      // arm phase 0, all
    // All CTAs' barriers + slot0 zeros visible before any peer pushes.
    asm volatile("barrier.cluster.arrive.aligned;" ::: "memory");
    asm volatile("barrier.cluster.wait.aligned;"   ::: "memory");

    const int bb = tid >> 5;   // reducer batch (tid<128)
    const int jj = tid & 31;
    float c = 0.f;             // cell state (tid<128)
    int par = 0;               // per-slot phase parity bits
    int rs = 0;                // t % 3

    // Prefetch Xp for t=0.
    const float* xp_base = Xp + ((size_t)cl * 4 + bb) * 1024 + (int)r * 32 + jj;
    float xc0 = 0.f, xc1 = 0.f, xc2 = 0.f, xc3 = 0.f;
    if (tid < 128) {
        xc0 = xp_base[0]; xc1 = xp_base[256];
        xc2 = xp_base[512]; xc3 = xp_base[768];
    }

    for (int t = 0; t < T_STEPS; ++t) {
        const int ws = (rs == 2) ? 0 : rs + 1;

        // Wait for this step's h block (rank w only). t=0: prefilled zeros.
        if (t > 0)
            mbar_wait(mb_s + (rs * 8 + w) * 8, (par >> rs) & 1);

        // Prefetch Xp for t+1 (consumed next iteration; ~full step of slack).
        float xn0 = 0.f, xn1 = 0.f, xn2 = 0.f, xn3 = 0.f;
        if (tid < 128 && t + 1 < T_STEPS) {
            const float* xp = xp_base + (size_t)(t + 1) * 64 * 1024;
            xn0 = xp[0]; xn1 = xp[256]; xn2 = xp[512]; xn3 = xp[768];
        }

        // Dot phase: warp w consumes rank-block w of slot rs.
        float2 acc[4][4];
#pragma unroll
        for (int rr = 0; rr < 4; ++rr)
#pragma unroll
            for (int b = 0; b < 4; ++b) acc[rr][b] = make_float2(0.f, 0.f);

        const float* hb = hsm + rs * 1024 + w * 128;   // [batch][32]
#pragma unroll
        for (int k2 = 0; k2 < 16; ++k2) {
            float2 h0 = *(const float2*)(hb + 2 * k2);
            float2 h1 = *(const float2*)(hb + 32 + 2 * k2);
            float2 h2 = *(const float2*)(hb + 64 + 2 * k2);
            float2 h3 = *(const float2*)(hb + 96 + 2 * k2);
#pragma unroll
            for (int rr = 0; rr < 4; ++rr) {
                ffma2(acc[rr][0], wreg[rr][k2], h0);
                ffma2(acc[rr][1], wreg[rr][k2], h1);
                ffma2(acc[rr][2], wreg[rr][k2], h2);
                ffma2(acc[rr][3], wreg[rr][k2], h3);
            }
        }
        // Gate-major partials: one float4 (i,f,g,o) per (batch, jj).
#pragma unroll
        for (int b = 0; b < 4; ++b) {
            part[w][b][lane] = make_float4(acc[0][b].x + acc[0][b].y,
                                           acc[1][b].x + acc[1][b].y,
                                           acc[2][b].x + acc[2][b].y,
                                           acc[3][b].x + acc[3][b].y);
        }
        __syncthreads();

        // Re-arm consumed slot's barriers for its next phase (arrivals are
        // >= 2 steps downstream through our own scatter -> race-free).
        if (t > 0 && tid < 8)
            mbar_expect_tx(mb_s + (rs * 8 + tid) * 8, 512u);

        if (tid < 128) {
            float s0 = xc0, s1 = xc1, s2 = xc2, s3 = xc3;
#pragma unroll
            for (int w8 = 0; w8 < 8; ++w8) {
                float4 p = part[w8][bb][jj];
                s0 += p.x; s1 += p.y; s2 += p.z; s3 += p.w;
            }
            float ig = __fdividef(1.f, 1.f + __expf(-s0));
            float fg = __fdividef(1.f, 1.f + __expf(-s1));
            float e2 = __expf(2.f * s2);
            float gg = __fdividef(e2 - 1.f, e2 + 1.f);
            float og = __fdividef(1.f, 1.f + __expf(-s3));
            c = fg * c + ig * gg;
            float ec = __expf(2.f * c);
            float h = og * __fdividef(ec - 1.f, ec + 1.f);
            hstage[tid] = h;                       // tid == bb*32 + jj
        }
        __syncthreads();

        // Coalesced scatter: each of 256 threads pushes ONE float4 of this
        // rank's h block to peer sdst's slot ws (16B st.async messages).
        if (t < T_STEPS - 1) {
            float4 v = ((const float4*)hstage)[sq];
            asm volatile(
                "st.async.shared::cluster.mbarrier::complete_tx::bytes"
                ".v4.f32 [%0], {%1,%2,%3,%4}, [%5];"
                :: "r"(sc_data_base + (uint32_t)ws * 4096u),
                   "f"(v.x), "f"(v.y), "f"(v.z), "f"(v.w),
                   "r"(sc_mbar_base + (uint32_t)ws * 64u)
                : "memory");
        }

        // Batched global h store (32 threads, STG.128, off the critical path).
        if (tid < 32) {
            const int sb = tid >> 3;       // batch 0..3
            const int qq = tid & 7;        // quad within row
            float4 v = ((const float4*)hstage)[sb * 8 + qq];
            *(float4*)(hs + ((size_t)t * 64 + cl * 4 + sb) * 256
                          + (int)r * 32 + qq * 4) = v;
        }

        // Rotate prefetched Xp.
        xc0 = xn0; xc1 = xn1; xc2 = xn2; xc3 = xn3;

        if (t > 0) par ^= (1 << rs);   // phase consumed this step
        rs = (rs == 2) ? 0 : rs + 1;
    }

    asm volatile("barrier.cluster.arrive.aligned;" ::: "memory");
    asm volatile("barrier.cluster.wait.aligned;"   ::: "memory");
}

// ---------------------------------------------------------------------------
// Launch
// ---------------------------------------------------------------------------
extern "C" void kernel_launch(void* const* d_in, const int* in_sizes, int n_in,
                              void* d_out, int out_size)
{
    const float* inputs = (const float*)d_in[0];
    const float* W_ih   = (const float*)d_in[1];
    const float* W_hh   = (const float*)d_in[2];
    const float* b_ih   = (const float*)d_in[3];
    const float* b_hh   = (const float*)d_in[4];
    const float* W_fc   = (const float*)d_in[5];
    const float* b_fc   = (const float*)d_in[6];
    float* out = (float*)d_out;

    float *Xp, *hsbuf;
    cudaGetSymbolAddress((void**)&Xp, g_Xp);
    cudaGetSymbolAddress((void**)&hsbuf, g_hs);

    // 1) Xp = inputs @ W_ih^T + (b_ih + b_hh)   [131072 x 1024], 3xTF32
    {
        dim3 grid(MROWS / 128, G4 / 128);
        tgemm128<<<grid, 256>>>(inputs, W_ih, b_ih, b_hh, Xp, INSZ, G4);
    }

    // 2) LSTM recurrence (clustered persistent kernel) -> hs [131072 x 256]
    {
        cudaLaunchConfig_t cfg = {};
        cfg.gridDim = dim3(128, 1, 1);
        cfg.blockDim = dim3(256, 1, 1);
        cfg.dynamicSmemBytes = 0;
        cfg.stream = 0;
        cudaLaunchAttribute attr[1];
        attr[0].id = cudaLaunchAttributeClusterDimension;
        attr[0].val.clusterDim.x = 8;
        attr[0].val.clusterDim.y = 1;
        attr[0].val.clusterDim.z = 1;
        cfg.attrs = attr;
        cfg.numAttrs = 1;
        cudaLaunchKernelEx(&cfg, lstm_rec_kernel, W_hh, (const float*)Xp, hsbuf);
    }

    // 3) out = hs @ W_fc^T + b_fc   [131072 x 128], 3xTF32
    {
        dim3 grid(MROWS / 128, OUTSZ / 128);
        tgemm128<<<grid, 256>>>(hsbuf, W_fc, b_fc, (const float*)nullptr, out,
                                HID, OUTSZ);
    }
}

// round 9
// speedup vs baseline: 1.2152x; 1.2152x over previous
#include <cuda_runtime.h>
#include <cuda_fp16.h>
#include <cstdint>

// ---------------------------------------------------------------------------
// Problem constants
// ---------------------------------------------------------------------------
#define T_STEPS 2048
#define BATCH   64
#define INSZ    512
#define HID     256
#define G4      1024      // 4*HID
#define OUTSZ   128
#define MROWS   (T_STEPS * BATCH)   // 131072

// Scratch (device globals: allocation-free per harness rules)
__device__ float g_Xp[(size_t)MROWS * G4];   // input projection + biases
__device__ float g_hs[(size_t)MROWS * HID];  // hidden states

// ---------------------------------------------------------------------------
// Packed fp32x2 FMA (SASS FFMA2) — used in the recurrence.
// ---------------------------------------------------------------------------
__device__ __forceinline__ void ffma2(float2& d, const float2& a, const float2& b)
{
    asm("fma.rn.f32x2 %0, %1, %2, %0;"
        : "+l"(reinterpret_cast<unsigned long long&>(d))
        : "l"(reinterpret_cast<const unsigned long long&>(a)),
          "l"(reinterpret_cast<const unsigned long long&>(b)));
}

// ---------------------------------------------------------------------------
// mbarrier helpers
// ---------------------------------------------------------------------------
__device__ __forceinline__ void mbar_init(uint32_t addr, uint32_t count)
{
    asm volatile("mbarrier.init.shared.b64 [%0], %1;" :: "r"(addr), "r"(count)
                 : "memory");
}
__device__ __forceinline__ void mbar_expect_tx(uint32_t addr, uint32_t bytes)
{
    asm volatile("mbarrier.arrive.expect_tx.shared.b64 _, [%0], %1;"
                 :: "r"(addr), "r"(bytes) : "memory");
}
__device__ __forceinline__ void mbar_wait(uint32_t addr, uint32_t parity)
{
    asm volatile(
        "{\n\t"
        ".reg .pred P;\n\t"
        "LW%=:\n\t"
        "mbarrier.try_wait.parity.acquire.cta.shared::cta.b64 P, [%0], %1;\n\t"
        "@P bra LD%=;\n\t"
        "bra LW%=;\n\t"
        "LD%=:\n\t"
        "}"
        :: "r"(addr), "r"(parity) : "memory");
}

// ---------------------------------------------------------------------------
// 3-term fp16 split GEMM (NT): C[m,n] = sum_k A[m,k]*B[n,k] + bias1[n](+bias2)
// mma.sync.m16n8k16.f16 with fp32 accumulate. x = hi(fp16) + lo(fp16);
// product = AhBh + AhBl + AlBh (AlBl ~2^-22, dropped).
// BM=BN=128, BK=16, 256 threads (8 warps, warp tile 64x32).
// smem stores (hi2, lo2) half2 pairs interleaved in one uint2 -> one LDS.64
// feeds both split fragments.
// Requires M%128==0, N%128==0, K%16==0.
// ---------------------------------------------------------------------------
#define MMA_F16(d, a0, a1, a2, a3, b0, b1)                                    \
    asm("mma.sync.aligned.m16n8k16.row.col.f32.f16.f16.f32 "                   \
        "{%0,%1,%2,%3},{%4,%5,%6,%7},{%8,%9},{%0,%1,%2,%3};"                   \
        : "+f"((d)[0]), "+f"((d)[1]), "+f"((d)[2]), "+f"((d)[3])               \
        : "r"(a0), "r"(a1), "r"(a2), "r"(a3), "r"(b0), "r"(b1))

// Split two consecutive fp32 values into (hi half2, lo half2).
__device__ __forceinline__ uint2 split_h2(float x, float y)
{
    __half2 hi = __floats2half2_rn(x, y);
    float2 hf = __half22float2(hi);
    __half2 lo = __floats2half2_rn(x - hf.x, y - hf.y);
    uint2 r;
    r.x = *(uint32_t*)&hi;
    r.y = *(uint32_t*)&lo;
    return r;
}

#define HPAD 10   // uint2 row stride (8 k-pairs + 2 pad)

__global__ void __launch_bounds__(256)
hgemm128(const float* __restrict__ A, const float* __restrict__ Bm,
         const float* __restrict__ bias1, const float* __restrict__ bias2,
         float* __restrict__ C, int K, int N)
{
    __shared__ uint2 As[128][HPAD];   // [row][kpair] = (hi half2, lo half2)
    __shared__ uint2 Bs[128][HPAD];

    const int tid  = threadIdx.x;
    const int lane = tid & 31;
    const int warp = tid >> 5;
    const int wm = warp & 1;           // 0..1 : 64 M-rows each
    const int wn = warp >> 1;          // 0..3 : 32 N-cols each
    const int g  = lane >> 2;          // 0..7
    const int t  = lane & 3;           // 0..3

    const size_t m0 = (size_t)blockIdx.x * 128;
    const int    n0 = blockIdx.y * 128;

    // Fill mapping: 2 threads per row; each converts 8 consecutive k values.
    const int frow = tid >> 1;         // 0..127
    const int fc   = (tid & 1) * 8;    // 0 or 8
    const float* Ag = A  + (m0 + frow) * (size_t)K + fc;
    const float* Bg = Bm + (size_t)(n0 + frow) * K + fc;

    float acc[4][4][4];
#pragma unroll
    for (int i = 0; i < 4; ++i)
#pragma unroll
        for (int j = 0; j < 4; ++j)
#pragma unroll
            for (int q = 0; q < 4; ++q) acc[i][j][q] = 0.f;

    for (int k0 = 0; k0 < K; k0 += 16) {
        float4 av0 = *(const float4*)(Ag + k0);
        float4 av1 = *(const float4*)(Ag + k0 + 4);
        float4 bv0 = *(const float4*)(Bg + k0);
        float4 bv1 = *(const float4*)(Bg + k0 + 4);
        __syncthreads();
        {
            const int p0 = fc >> 1;    // first k-pair index (0 or 4)
            As[frow][p0 + 0] = split_h2(av0.x, av0.y);
            As[frow][p0 + 1] = split_h2(av0.z, av0.w);
            As[frow][p0 + 2] = split_h2(av1.x, av1.y);
            As[frow][p0 + 3] = split_h2(av1.z, av1.w);
            Bs[frow][p0 + 0] = split_h2(bv0.x, bv0.y);
            Bs[frow][p0 + 1] = split_h2(bv0.z, bv0.w);
            Bs[frow][p0 + 2] = split_h2(bv1.x, bv1.y);
            Bs[frow][p0 + 3] = split_h2(bv1.z, bv1.w);
        }
        __syncthreads();

        // Fragments: A regs (row g / g+8, kpair t / t+4); B regs (n, t / t+4).
        uint32_t ah[4][4], al[4][4], bh[4][2], bl[4][2];
#pragma unroll
        for (int i = 0; i < 4; ++i) {
            const int row = wm * 64 + i * 16 + g;
            uint2 q00 = As[row][t];
            uint2 q10 = As[row + 8][t];
            uint2 q01 = As[row][t + 4];
            uint2 q11 = As[row + 8][t + 4];
            ah[i][0] = q00.x; ah[i][1] = q10.x; ah[i][2] = q01.x; ah[i][3] = q11.x;
            al[i][0] = q00.y; al[i][1] = q10.y; al[i][2] = q01.y; al[i][3] = q11.y;
        }
#pragma unroll
        for (int j = 0; j < 4; ++j) {
            const int n = wn * 32 + j * 8 + g;
            uint2 p0 = Bs[n][t];
            uint2 p1 = Bs[n][t + 4];
            bh[j][0] = p0.x; bh[j][1] = p1.x;
            bl[j][0] = p0.y; bl[j][1] = p1.y;
        }
#pragma unroll
        for (int i = 0; i < 4; ++i)
#pragma unroll
            for (int j = 0; j < 4; ++j) {
                MMA_F16(acc[i][j], ah[i][0], ah[i][1], ah[i][2], ah[i][3],
                        bh[j][0], bh[j][1]);
                MMA_F16(acc[i][j], ah[i][0], ah[i][1], ah[i][2], ah[i][3],
                        bl[j][0], bl[j][1]);
                MMA_F16(acc[i][j], al[i][0], al[i][1], al[i][2], al[i][3],
                        bh[j][0], bh[j][1]);
            }
    }

    // Epilogue: bias + stores (c0,c1 row g; c2,c3 row g+8; cols 2t,2t+1).
#pragma unroll
    for (int j = 0; j < 4; ++j) {
        int col = n0 + wn * 32 + j * 8 + 2 * t;
        float b0 = bias1[col], b1 = bias1[col + 1];
        if (bias2) { b0 += bias2[col]; b1 += bias2[col + 1]; }
#pragma unroll
        for (int i = 0; i < 4; ++i) {
            size_t row = m0 + wm * 64 + i * 16 + g;
            *(float2*)(C + row * N + col) =
                make_float2(acc[i][j][0] + b0, acc[i][j][1] + b1);
            *(float2*)(C + (row + 8) * N + col) =
                make_float2(acc[i][j][2] + b0, acc[i][j][3] + b1);
        }
    }
}

// ---------------------------------------------------------------------------
// LSTM recurrence (R6 version — best measured): per-(slot,rank) mbarriers +
// st.async 4B direct scatter. 16 clusters x 8 CTAs x 256 threads.
// ---------------------------------------------------------------------------
__global__ void __launch_bounds__(256, 1)
lstm_rec_kernel(const float* __restrict__ Whh,
                const float* __restrict__ Xp,
                float* __restrict__ hs)
{
    __shared__ float  hsm[3 * 1024];          // [slot][rank][batch][32]
    __shared__ float4 part[8][4][32];         // [warp][batch][jj] = 4 gates
    __shared__ __align__(8) unsigned long long mbar[24];  // [slot][rank]

    const int tid  = threadIdx.x;
    const int lane = tid & 31;
    const int w    = tid >> 5;

    unsigned r;
    asm("mov.u32 %0, %%cluster_ctarank;" : "=r"(r));
    const int cl = blockIdx.x >> 3;

    const uint32_t hsm_s = (uint32_t)__cvta_generic_to_shared(hsm);
    const uint32_t mb_s  = (uint32_t)__cvta_generic_to_shared(mbar);

    uint32_t pd[8], pm[8];
#pragma unroll
    for (int dst = 0; dst < 8; ++dst) {
        asm("mapa.shared::cluster.u32 %0, %1, %2;"
            : "=r"(pd[dst]) : "r"(hsm_s), "r"(dst));
        asm("mapa.shared::cluster.u32 %0, %1, %2;"
            : "=r"(pm[dst]) : "r"(mb_s), "r"(dst));
    }

    float2 wreg[4][16];
#pragma unroll
    for (int rr = 0; rr < 4; ++rr) {
        int grow = rr * 256 + (int)r * 32 + lane;
        const float2* wp = (const float2*)(Whh + (size_t)grow * 256 + w * 32);
#pragma unroll
        for (int k2 = 0; k2 < 16; ++k2) wreg[rr][k2] = wp[k2];
    }
    for (int i = tid; i < 3 * 1024; i += 256) hsm[i] = 0.f;
    if (tid < 24) mbar_init(mb_s + tid * 8, 1);
    __syncthreads();
    if (tid < 24) mbar_expect_tx(mb_s + tid * 8, 512u);
    asm volatile("barrier.cluster.arrive.aligned;" ::: "memory");
    asm volatile("barrier.cluster.wait.aligned;"   ::: "memory");

    const int bb = tid >> 5;
    const int jj = tid & 31;
    float c = 0.f;
    int par = 0;
    int rs = 0;

    const float* xp_base = Xp + ((size_t)cl * 4 + bb) * 1024 + (int)r * 32 + jj;
    float xc0 = 0.f, xc1 = 0.f, xc2 = 0.f, xc3 = 0.f;
    if (tid < 128) {
        xc0 = xp_base[0]; xc1 = xp_base[256];
        xc2 = xp_base[512]; xc3 = xp_base[768];
    }

    for (int t = 0; t < T_STEPS; ++t) {
        const int ws = (rs == 2) ? 0 : rs + 1;

        if (t > 0)
            mbar_wait(mb_s + (rs * 8 + w) * 8, (par >> rs) & 1);

        float xn0 = 0.f, xn1 = 0.f, xn2 = 0.f, xn3 = 0.f;
        if (tid < 128 && t + 1 < T_STEPS) {
            const float* xp = xp_base + (size_t)(t + 1) * 64 * 1024;
            xn0 = xp[0]; xn1 = xp[256]; xn2 = xp[512]; xn3 = xp[768];
        }

        float2 acc[4][4];
#pragma unroll
        for (int rr = 0; rr < 4; ++rr)
#pragma unroll
            for (int b = 0; b < 4; ++b) acc[rr][b] = make_float2(0.f, 0.f);

        const float* hb = hsm + rs * 1024 + w * 128;
#pragma unroll
        for (int k2 = 0; k2 < 16; ++k2) {
            float2 h0 = *(const float2*)(hb + 2 * k2);
            float2 h1 = *(const float2*)(hb + 32 + 2 * k2);
            float2 h2 = *(const float2*)(hb + 64 + 2 * k2);
            float2 h3 = *(const float2*)(hb + 96 + 2 * k2);
#pragma unroll
            for (int rr = 0; rr < 4; ++rr) {
                ffma2(acc[rr][0], wreg[rr][k2], h0);
                ffma2(acc[rr][1], wreg[rr][k2], h1);
                ffma2(acc[rr][2], wreg[rr][k2], h2);
                ffma2(acc[rr][3], wreg[rr][k2], h3);
            }
        }
#pragma unroll
        for (int b = 0; b < 4; ++b) {
            part[w][b][lane] = make_float4(acc[0][b].x + acc[0][b].y,
                                           acc[1][b].x + acc[1][b].y,
                                           acc[2][b].x + acc[2][b].y,
                                           acc[3][b].x + acc[3][b].y);
        }
        __syncthreads();

        if (t > 0 && tid < 8)
            mbar_expect_tx(mb_s + (rs * 8 + tid) * 8, 512u);

        if (tid < 128) {
            float s0 = xc0, s1 = xc1, s2 = xc2, s3 = xc3;
#pragma unroll
            for (int w8 = 0; w8 < 8; ++w8) {
                float4 p = part[w8][bb][jj];
                s0 += p.x; s1 += p.y; s2 += p.z; s3 += p.w;
            }
            float ig = __fdividef(1.f, 1.f + __expf(-s0));
            float fg = __fdividef(1.f, 1.f + __expf(-s1));
            float e2 = __expf(2.f * s2);
            float gg = __fdividef(e2 - 1.f, e2 + 1.f);
            float og = __fdividef(1.f, 1.f + __expf(-s3));
            c = fg * c + ig * gg;
            float ec = __expf(2.f * c);
            float h = og * __fdividef(ec - 1.f, ec + 1.f);

            if (t < T_STEPS - 1) {
                uint32_t hv = __float_as_uint(h);
                uint32_t doff = (uint32_t)ws * 4096u + r * 512u
                              + (uint32_t)tid * 4u;
                uint32_t moff = ((uint32_t)ws * 8u + r) * 8u;
#pragma unroll
                for (int dst = 0; dst < 8; ++dst) {
                    asm volatile(
                        "st.async.shared::cluster.mbarrier::complete_tx::bytes"
                        ".u32 [%0], %1, [%2];"
                        :: "r"(pd[dst] + doff), "r"(hv), "r"(pm[dst] + moff)
                        : "memory");
                }
            }
            hs[((size_t)t * 64 + cl * 4 + bb) * 256 + (int)r * 32 + jj] = h;
        }

        xc0 = xn0; xc1 = xn1; xc2 = xn2; xc3 = xn3;

        if (t > 0) par ^= (1 << rs);
        rs = (rs == 2) ? 0 : rs + 1;
    }

    asm volatile("barrier.cluster.arrive.aligned;" ::: "memory");
    asm volatile("barrier.cluster.wait.aligned;"   ::: "memory");
}

// ---------------------------------------------------------------------------
// Launch
// ---------------------------------------------------------------------------
extern "C" void kernel_launch(void* const* d_in, const int* in_sizes, int n_in,
                              void* d_out, int out_size)
{
    const float* inputs = (const float*)d_in[0];
    const float* W_ih   = (const float*)d_in[1];
    const float* W_hh   = (const float*)d_in[2];
    const float* b_ih   = (const float*)d_in[3];
    const float* b_hh   = (const float*)d_in[4];
    const float* W_fc   = (const float*)d_in[5];
    const float* b_fc   = (const float*)d_in[6];
    float* out = (float*)d_out;

    float *Xp, *hsbuf;
    cudaGetSymbolAddress((void**)&Xp, g_Xp);
    cudaGetSymbolAddress((void**)&hsbuf, g_hs);

    // 1) Xp = inputs @ W_ih^T + (b_ih + b_hh)   [131072 x 1024], fp16x3 HMMA
    {
        dim3 grid(MROWS / 128, G4 / 128);
        hgemm128<<<grid, 256>>>(inputs, W_ih, b_ih, b_hh, Xp, INSZ, G4);
    }

    // 2) LSTM recurrence (clustered persistent kernel) -> hs [131072 x 256]
    {
        cudaLaunchConfig_t cfg = {};
        cfg.gridDim = dim3(128, 1, 1);
        cfg.blockDim = dim3(256, 1, 1);
        cfg.dynamicSmemBytes = 0;
        cfg.stream = 0;
        cudaLaunchAttribute attr[1];
        attr[0].id = cudaLaunchAttributeClusterDimension;
        attr[0].val.clusterDim.x = 8;
        attr[0].val.clusterDim.y = 1;
        attr[0].val.clusterDim.z = 1;
        cfg.attrs = attr;
        cfg.numAttrs = 1;
        cudaLaunchKernelEx(&cfg, lstm_rec_kernel, W_hh, (const float*)Xp, hsbuf);
    }

    // 3) out = hs @ W_fc^T + b_fc   [131072 x 128], fp16x3 HMMA
    {
        dim3 grid(MROWS / 128, OUTSZ / 128);
        hgemm128<<<grid, 256>>>(hsbuf, W_fc, b_fc, (const float*)nullptr, out,
                                HID, OUTSZ);
    }
}

// round 10
// speedup vs baseline: 1.3389x; 1.1018x over previous
#include <cuda_runtime.h>
#include <cuda_fp16.h>
#include <cstdint>

// ---------------------------------------------------------------------------
// Problem constants
// ---------------------------------------------------------------------------
#define T_STEPS 2048
#define BATCH   64
#define INSZ    512
#define HID     256
#define G4      1024      // 4*HID
#define OUTSZ   128
#define MROWS   (T_STEPS * BATCH)   // 131072

// Scratch (device globals: allocation-free per harness rules)
__device__ float g_Xp[(size_t)MROWS * G4];                 // input projection
__device__ uint4 g_Ah[(size_t)MROWS * INSZ / 4];           // inputs, fp16 hi/lo split
__device__ uint4 g_Wih[(size_t)G4 * INSZ / 4];             // W_ih split
__device__ uint4 g_hsh[(size_t)MROWS * HID / 4];           // hs, split (written by rec)
__device__ uint4 g_Wfc[(size_t)OUTSZ * HID / 4];           // W_fc split

// ---------------------------------------------------------------------------
// Helpers
// ---------------------------------------------------------------------------
__device__ __forceinline__ void ffma2(float2& d, const float2& a, const float2& b)
{
    asm("fma.rn.f32x2 %0, %1, %2, %0;"
        : "+l"(reinterpret_cast<unsigned long long&>(d))
        : "l"(reinterpret_cast<const unsigned long long&>(a)),
          "l"(reinterpret_cast<const unsigned long long&>(b)));
}

__device__ __forceinline__ uint2 split_h2(float x, float y)
{
    __half2 hi = __floats2half2_rn(x, y);
    float2 hf = __half22float2(hi);
    __half2 lo = __floats2half2_rn(x - hf.x, y - hf.y);
    uint2 r;
    r.x = *(uint32_t*)&hi;
    r.y = *(uint32_t*)&lo;
    return r;
}

__device__ __forceinline__ void mbar_init(uint32_t addr, uint32_t count)
{
    asm volatile("mbarrier.init.shared.b64 [%0], %1;" :: "r"(addr), "r"(count)
                 : "memory");
}
__device__ __forceinline__ void mbar_expect_tx(uint32_t addr, uint32_t bytes)
{
    asm volatile("mbarrier.arrive.expect_tx.shared.b64 _, [%0], %1;"
                 :: "r"(addr), "r"(bytes) : "memory");
}
__device__ __forceinline__ void mbar_wait(uint32_t addr, uint32_t parity)
{
    asm volatile(
        "{\n\t"
        ".reg .pred P;\n\t"
        "LW%=:\n\t"
        "mbarrier.try_wait.parity.acquire.cta.shared::cta.b64 P, [%0], %1;\n\t"
        "@P bra LD%=;\n\t"
        "bra LW%=;\n\t"
        "LD%=:\n\t"
        "}"
        :: "r"(addr), "r"(parity) : "memory");
}

// ---------------------------------------------------------------------------
// Pre-split: fp32 -> (hi fp16, lo fp16) packed as uint2 per fp32-pair.
// ---------------------------------------------------------------------------
__global__ void presplit(const float4* __restrict__ in, uint4* __restrict__ out,
                         int n4)
{
    for (int i = blockIdx.x * blockDim.x + threadIdx.x; i < n4;
         i += gridDim.x * blockDim.x) {
        float4 v = in[i];
        uint2 a = split_h2(v.x, v.y);
        uint2 b = split_h2(v.z, v.w);
        out[i] = make_uint4(a.x, a.y, b.x, b.y);
    }
}

// ---------------------------------------------------------------------------
// 3-term fp16 split GEMM (NT), PRE-SPLIT operands:
// C[m,n] = sum_k A[m,k]*B[n,k] + bias1[n] (+bias2).
// A,B given as uint2 streams: kpair -> (hi half2, lo half2).
// BM=BN=128, BK=16 (8 kpairs), 256 threads, warp tile 64x32,
// mma.sync.m16n8k16.f16 fp32-accum; AhBh + AhBl + AlBh.
// ---------------------------------------------------------------------------
#define MMA_F16(d, a0, a1, a2, a3, b0, b1)                                    \
    asm("mma.sync.aligned.m16n8k16.row.col.f32.f16.f16.f32 "                   \
        "{%0,%1,%2,%3},{%4,%5,%6,%7},{%8,%9},{%0,%1,%2,%3};"                   \
        : "+f"((d)[0]), "+f"((d)[1]), "+f"((d)[2]), "+f"((d)[3])               \
        : "r"(a0), "r"(a1), "r"(a2), "r"(a3), "r"(b0), "r"(b1))

#define HPAD 10   // uint2 row stride (8 kpairs + 2 pad); 80B -> 16B aligned rows

__global__ void __launch_bounds__(256)
hgemm_pre(const uint2* __restrict__ Ah, const uint2* __restrict__ Bh,
          const float* __restrict__ bias1, const float* __restrict__ bias2,
          float* __restrict__ C, int K2, int N)
{
    __shared__ uint2 As[128][HPAD];
    __shared__ uint2 Bs[128][HPAD];

    const int tid  = threadIdx.x;
    const int lane = tid & 31;
    const int warp = tid >> 5;
    const int wm = warp & 1;
    const int wn = warp >> 1;
    const int g  = lane >> 2;
    const int t  = lane & 3;

    const size_t m0 = (size_t)blockIdx.x * 128;
    const int    n0 = blockIdx.y * 128;

    const int frow = tid >> 1;
    const int fc2  = (tid & 1) * 4;     // kpair offset 0 or 4
    const uint2* Ag = Ah + (m0 + frow) * (size_t)K2 + fc2;
    const uint2* Bg = Bh + (size_t)(n0 + frow) * K2 + fc2;

    float acc[4][4][4];
#pragma unroll
    for (int i = 0; i < 4; ++i)
#pragma unroll
        for (int j = 0; j < 4; ++j)
#pragma unroll
            for (int q = 0; q < 4; ++q) acc[i][j][q] = 0.f;

    for (int kb = 0; kb < K2; kb += 8) {
        uint4 a0 = *(const uint4*)(Ag + kb);
        uint4 a1 = *(const uint4*)(Ag + kb + 2);
        uint4 b0 = *(const uint4*)(Bg + kb);
        uint4 b1 = *(const uint4*)(Bg + kb + 2);
        __syncthreads();
        *(uint4*)&As[frow][fc2]     = a0;
        *(uint4*)&As[frow][fc2 + 2] = a1;
        *(uint4*)&Bs[frow][fc2]     = b0;
        *(uint4*)&Bs[frow][fc2 + 2] = b1;
        __syncthreads();

        uint32_t ah[4][4], al[4][4], bh[4][2], bl[4][2];
#pragma unroll
        for (int i = 0; i < 4; ++i) {
            const int row = wm * 64 + i * 16 + g;
            uint2 q00 = As[row][t];
            uint2 q10 = As[row + 8][t];
            uint2 q01 = As[row][t + 4];
            uint2 q11 = As[row + 8][t + 4];
            ah[i][0] = q00.x; ah[i][1] = q10.x; ah[i][2] = q01.x; ah[i][3] = q11.x;
            al[i][0] = q00.y; al[i][1] = q10.y; al[i][2] = q01.y; al[i][3] = q11.y;
        }
#pragma unroll
        for (int j = 0; j < 4; ++j) {
            const int n = wn * 32 + j * 8 + g;
            uint2 p0 = Bs[n][t];
            uint2 p1 = Bs[n][t + 4];
            bh[j][0] = p0.x; bh[j][1] = p1.x;
            bl[j][0] = p0.y; bl[j][1] = p1.y;
        }
#pragma unroll
        for (int i = 0; i < 4; ++i)
#pragma unroll
            for (int j = 0; j < 4; ++j) {
                MMA_F16(acc[i][j], ah[i][0], ah[i][1], ah[i][2], ah[i][3],
                        bh[j][0], bh[j][1]);
                MMA_F16(acc[i][j], ah[i][0], ah[i][1], ah[i][2], ah[i][3],
                        bl[j][0], bl[j][1]);
                MMA_F16(acc[i][j], al[i][0], al[i][1], al[i][2], al[i][3],
                        bh[j][0], bh[j][1]);
            }
    }

#pragma unroll
    for (int j = 0; j < 4; ++j) {
        int col = n0 + wn * 32 + j * 8 + 2 * t;
        float b0 = bias1[col], b1 = bias1[col + 1];
        if (bias2) { b0 += bias2[col]; b1 += bias2[col + 1]; }
#pragma unroll
        for (int i = 0; i < 4; ++i) {
            size_t row = m0 + wm * 64 + i * 16 + g;
            *(float2*)(C + row * N + col) =
                make_float2(acc[i][j][0] + b0, acc[i][j][1] + b1);
            *(float2*)(C + (row + 8) * N + col) =
                make_float2(acc[i][j][2] + b0, acc[i][j][3] + b1);
        }
    }
}

// ---------------------------------------------------------------------------
// LSTM recurrence v6: two-group software pipeline.
// 16 clusters x 8 CTAs x 256 threads. Cluster cl owns batches [cl*4, cl*4+4);
// group g in {0,1} covers batches cl*4 + g*2 + {0,1}.
// Per step: dotA -> redA (warps 0-1) -> dotB -> redB (warps 2-3).
// Group g's scatter (end of red_g at t) is consumed by dot_g at t+1 — a full
// opposite-group phase of slack hides DSMEM latency + cluster skew.
// Rings: hsm[g][slot=3][rank=8][64]; barriers mbar[g][slot][rank],
// expect_tx = 256B (64 reducer threads x 4B st.async).
// hs emitted PRE-SPLIT (uint2 per fp32-pair) for the FC GEMM.
// ---------------------------------------------------------------------------
__global__ void __launch_bounds__(256, 1)
lstm_rec_kernel(const float* __restrict__ Whh,
                const float* __restrict__ Xp,
                uint2* __restrict__ hs_h)
{
    __shared__ float  hsm[2][3][8][64];        // [g][slot][rank][bb*32+jj]
    __shared__ float4 part[2][8][2][32];       // [g][warp][bb][jj] = 4 gates
    __shared__ __align__(8) unsigned long long mbar[48];  // [g][slot][rank]

    const int tid  = threadIdx.x;
    const int lane = tid & 31;
    const int w    = tid >> 5;

    unsigned r;
    asm("mov.u32 %0, %%cluster_ctarank;" : "=r"(r));
    const int cl = blockIdx.x >> 3;

    const uint32_t hsm_s = (uint32_t)__cvta_generic_to_shared(hsm);
    const uint32_t mb_s  = (uint32_t)__cvta_generic_to_shared(mbar);

    uint32_t pd[8], pm[8];
#pragma unroll
    for (int dst = 0; dst < 8; ++dst) {
        asm("mapa.shared::cluster.u32 %0, %1, %2;"
            : "=r"(pd[dst]) : "r"(hsm_s), "r"(dst));
        asm("mapa.shared::cluster.u32 %0, %1, %2;"
            : "=r"(pm[dst]) : "r"(mb_s), "r"(dst));
    }

    // Weights: gate rr of output (r*32+lane), K chunk [w*32,(w+1)*32).
    float2 wreg[4][16];
#pragma unroll
    for (int rr = 0; rr < 4; ++rr) {
        int grow = rr * 256 + (int)r * 32 + lane;
        const float2* wp = (const float2*)(Whh + (size_t)grow * 256 + w * 32);
#pragma unroll
        for (int k2 = 0; k2 < 16; ++k2) wreg[rr][k2] = wp[k2];
    }
    for (int i = tid; i < 2 * 3 * 8 * 64; i += 256) ((float*)hsm)[i] = 0.f;
    if (tid < 48) mbar_init(mb_s + tid * 8, 1);
    __syncthreads();
    if (tid < 48) mbar_expect_tx(mb_s + tid * 8, 256u);   // arm phase 0, all
    asm volatile("barrier.cluster.arrive.aligned;" ::: "memory");
    asm volatile("barrier.cluster.wait.aligned;"   ::: "memory");

    // Reducer identity (tid<128): group mg = tid>>6, tl = tid&63.
    const int mg = tid >> 6;           // 0: warps 0-1, 1: warps 2-3
    const int tl = tid & 63;
    const int bb = tl >> 5;            // batch-in-group
    const int jj = tl & 31;
    float c = 0.f;
    int par = 0;                       // per-slot parity (shared by both groups)
    int rs = 0;

    const float* xp_base = Xp + ((size_t)cl * 4 + mg * 2 + bb) * 1024
                              + (int)r * 32 + jj;
    float xc0 = 0.f, xc1 = 0.f, xc2 = 0.f, xc3 = 0.f;
    if (tid < 128) {
        xc0 = xp_base[0]; xc1 = xp_base[256];
        xc2 = xp_base[512]; xc3 = xp_base[768];
    }

    for (int t = 0; t < T_STEPS; ++t) {
        const int ws = (rs == 2) ? 0 : rs + 1;

        // ============ group A (g=0) ============
        if (t > 0)
            mbar_wait(mb_s + ((0 * 3 + rs) * 8 + w) * 8, (par >> rs) & 1);

        // Prefetch Xp for t+1 (both groups' reducers).
        float xn0 = 0.f, xn1 = 0.f, xn2 = 0.f, xn3 = 0.f;
        if (tid < 128 && t + 1 < T_STEPS) {
            const float* xp = xp_base + (size_t)(t + 1) * 64 * 1024;
            xn0 = xp[0]; xn1 = xp[256]; xn2 = xp[512]; xn3 = xp[768];
        }

        {   // dot A
            float2 acc[4][2];
#pragma unroll
            for (int rr = 0; rr < 4; ++rr) {
                acc[rr][0] = make_float2(0.f, 0.f);
                acc[rr][1] = make_float2(0.f, 0.f);
            }
            const float* hb = &hsm[0][rs][w][0];
#pragma unroll
            for (int k2 = 0; k2 < 16; ++k2) {
                float2 h0 = *(const float2*)(hb + 2 * k2);
                float2 h1 = *(const float2*)(hb + 32 + 2 * k2);
#pragma unroll
                for (int rr = 0; rr < 4; ++rr) {
                    ffma2(acc[rr][0], wreg[rr][k2], h0);
                    ffma2(acc[rr][1], wreg[rr][k2], h1);
                }
            }
#pragma unroll
            for (int b = 0; b < 2; ++b)
                part[0][w][b][lane] = make_float4(acc[0][b].x + acc[0][b].y,
                                                  acc[1][b].x + acc[1][b].y,
                                                  acc[2][b].x + acc[2][b].y,
                                                  acc[3][b].x + acc[3][b].y);
        }
        __syncthreads();
        if (t > 0 && tid < 8)
            mbar_expect_tx(mb_s + ((0 * 3 + rs) * 8 + tid) * 8, 256u);

        // red A (warps 0-1)
        if (tid < 64) {
            float s0 = xc0, s1 = xc1, s2 = xc2, s3 = xc3;
#pragma unroll
            for (int w8 = 0; w8 < 8; ++w8) {
                float4 p = part[0][w8][bb][jj];
                s0 += p.x; s1 += p.y; s2 += p.z; s3 += p.w;
            }
            float ig = __fdividef(1.f, 1.f + __expf(-s0));
            float fg = __fdividef(1.f, 1.f + __expf(-s1));
            float e2 = __expf(2.f * s2);
            float gg = __fdividef(e2 - 1.f, e2 + 1.f);
            float og = __fdividef(1.f, 1.f + __expf(-s3));
            c = fg * c + ig * gg;
            float ec = __expf(2.f * c);
            float h = og * __fdividef(ec - 1.f, ec + 1.f);

            if (t < T_STEPS - 1) {
                uint32_t hv = __float_as_uint(h);
                uint32_t doff = (uint32_t)(0 * 6144 + ws * 2048 + (int)r * 256
                                           + tl * 4);
                uint32_t moff = (uint32_t)(((0 * 3 + ws) * 8 + (int)r) * 8);
#pragma unroll
                for (int dst = 0; dst < 8; ++dst)
                    asm volatile(
                        "st.async.shared::cluster.mbarrier::complete_tx::bytes"
                        ".u32 [%0], %1, [%2];"
                        :: "r"(pd[dst] + doff), "r"(hv), "r"(pm[dst] + moff)
                        : "memory");
            }
            // split hs store
            float hn = __shfl_down_sync(0xFFFFFFFFu, h, 1);
            if (!(jj & 1)) {
                uint2 sv = split_h2(h, hn);
                hs_h[((size_t)t * 64 + cl * 4 + bb) * 128
                     + (int)r * 16 + (jj >> 1)] = sv;
            }
        }

        // ============ group B (g=1) ============
        if (t > 0)
            mbar_wait(mb_s + ((1 * 3 + rs) * 8 + w) * 8, (par >> rs) & 1);

        {   // dot B
            float2 acc[4][2];
#pragma unroll
            for (int rr = 0; rr < 4; ++rr) {
                acc[rr][0] = make_float2(0.f, 0.f);
                acc[rr][1] = make_float2(0.f, 0.f);
            }
            const float* hb = &hsm[1][rs][w][0];
#pragma unroll
            for (int k2 = 0; k2 < 16; ++k2) {
                float2 h0 = *(const float2*)(hb + 2 * k2);
                float2 h1 = *(const float2*)(hb + 32 + 2 * k2);
#pragma unroll
                for (int rr = 0; rr < 4; ++rr) {
                    ffma2(acc[rr][0], wreg[rr][k2], h0);
                    ffma2(acc[rr][1], wreg[rr][k2], h1);
                }
            }
#pragma unroll
            for (int b = 0; b < 2; ++b)
                part[1][w][b][lane] = make_float4(acc[0][b].x + acc[0][b].y,
                                                  acc[1][b].x + acc[1][b].y,
                                                  acc[2][b].x + acc[2][b].y,
                                                  acc[3][b].x + acc[3][b].y);
        }
        __syncthreads();
        if (t > 0 && tid < 8)
            mbar_expect_tx(mb_s + ((1 * 3 + rs) * 8 + tid) * 8, 256u);

        // red B (warps 2-3)
        if (tid >= 64 && tid < 128) {
            float s0 = xc0, s1 = xc1, s2 = xc2, s3 = xc3;
#pragma unroll
            for (int w8 = 0; w8 < 8; ++w8) {
                float4 p = part[1][w8][bb][jj];
                s0 += p.x; s1 += p.y; s2 += p.z; s3 += p.w;
            }
            float ig = __fdividef(1.f, 1.f + __expf(-s0));
            float fg = __fdividef(1.f, 1.f + __expf(-s1));
            float e2 = __expf(2.f * s2);
            float gg = __fdividef(e2 - 1.f, e2 + 1.f);
            float og = __fdividef(1.f, 1.f + __expf(-s3));
            c = fg * c + ig * gg;
            float ec = __expf(2.f * c);
            float h = og * __fdividef(ec - 1.f, ec + 1.f);

            if (t < T_STEPS - 1) {
                uint32_t hv = __float_as_uint(h);
                uint32_t doff = (uint32_t)(1 * 6144 + ws * 2048 + (int)r * 256
                                           + tl * 4);
                uint32_t moff = (uint32_t)(((1 * 3 + ws) * 8 + (int)r) * 8);
#pragma unroll
                for (int dst = 0; dst < 8; ++dst)
                    asm volatile(
                        "st.async.shared::cluster.mbarrier::complete_tx::bytes"
                        ".u32 [%0], %1, [%2];"
                        :: "r"(pd[dst] + doff), "r"(hv), "r"(pm[dst] + moff)
                        : "memory");
            }
            float hn = __shfl_down_sync(0xFFFFFFFFu, h, 1);
            if (!(jj & 1)) {
                uint2 sv = split_h2(h, hn);
                hs_h[((size_t)t * 64 + cl * 4 + 2 + bb) * 128
                     + (int)r * 16 + (jj >> 1)] = sv;
            }
        }

        xc0 = xn0; xc1 = xn1; xc2 = xn2; xc3 = xn3;
        if (t > 0) par ^= (1 << rs);
        rs = ws;
    }

    asm volatile("barrier.cluster.arrive.aligned;" ::: "memory");
    asm volatile("barrier.cluster.wait.aligned;"   ::: "memory");
}

// ---------------------------------------------------------------------------
// Launch
// ---------------------------------------------------------------------------
extern "C" void kernel_launch(void* const* d_in, const int* in_sizes, int n_in,
                              void* d_out, int out_size)
{
    const float* inputs = (const float*)d_in[0];
    const float* W_ih   = (const float*)d_in[1];
    const float* W_hh   = (const float*)d_in[2];
    const float* b_ih   = (const float*)d_in[3];
    const float* b_hh   = (const float*)d_in[4];
    const float* W_fc   = (const float*)d_in[5];
    const float* b_fc   = (const float*)d_in[6];
    float* out = (float*)d_out;

    float *Xp;
    uint4 *Ah, *Wih, *hsh, *Wfc;
    cudaGetSymbolAddress((void**)&Xp,  g_Xp);
    cudaGetSymbolAddress((void**)&Ah,  g_Ah);
    cudaGetSymbolAddress((void**)&Wih, g_Wih);
    cudaGetSymbolAddress((void**)&hsh, g_hsh);
    cudaGetSymbolAddress((void**)&Wfc, g_Wfc);

    // 0) Pre-split fp32 -> fp16 hi/lo pairs.
    presplit<<<4096, 256>>>((const float4*)inputs, Ah, MROWS * INSZ / 4);
    presplit<<<512, 256>>>((const float4*)W_ih, Wih, G4 * INSZ / 4);
    presplit<<<32, 256>>>((const float4*)W_fc, Wfc, OUTSZ * HID / 4);

    // 1) Xp = inputs @ W_ih^T + (b_ih + b_hh)   [131072 x 1024]
    {
        dim3 grid(MROWS / 128, G4 / 128);
        hgemm_pre<<<grid, 256>>>((const uint2*)Ah, (const uint2*)Wih,
                                 b_ih, b_hh, Xp, INSZ / 2, G4);
    }

    // 2) LSTM recurrence -> hs (pre-split) [131072 x 256]
    {
        cudaLaunchConfig_t cfg = {};
        cfg.gridDim = dim3(128, 1, 1);
        cfg.blockDim = dim3(256, 1, 1);
        cfg.dynamicSmemBytes = 0;
        cfg.stream = 0;
        cudaLaunchAttribute attr[1];
        attr[0].id = cudaLaunchAttributeClusterDimension;
        attr[0].val.clusterDim.x = 8;
        attr[0].val.clusterDim.y = 1;
        attr[0].val.clusterDim.z = 1;
        cfg.attrs = attr;
        cfg.numAttrs = 1;
        cudaLaunchKernelEx(&cfg, lstm_rec_kernel, W_hh, (const float*)Xp,
                           (uint2*)hsh);
    }

    // 3) out = hs @ W_fc^T + b_fc   [131072 x 128]
    {
        dim3 grid(MROWS / 128, OUTSZ / 128);
        hgemm_pre<<<grid, 256>>>((const uint2*)hsh, (const uint2*)Wfc,
                                 b_fc, (const float*)nullptr, out,
                                 HID / 2, OUTSZ);
    }
}

// round 11
// speedup vs baseline: 1.3887x; 1.0372x over previous
#include <cuda_runtime.h>
#include <cuda_fp16.h>
#include <cstdint>

// ---------------------------------------------------------------------------
// Problem constants
// ---------------------------------------------------------------------------
#define T_STEPS 2048
#define BATCH   64
#define INSZ    512
#define HID     256
#define G4      1024      // 4*HID
#define OUTSZ   128
#define MROWS   (T_STEPS * BATCH)   // 131072

// Scratch (device globals: allocation-free per harness rules)
__device__ float g_Xp[(size_t)MROWS * G4];                 // input projection
__device__ uint4 g_Ah[(size_t)MROWS * INSZ / 4];           // inputs, fp16 hi/lo split
__device__ uint4 g_Wih[(size_t)G4 * INSZ / 4];             // W_ih split
__device__ uint4 g_hsh[(size_t)MROWS * HID / 4];           // hs, split (written by rec)
__device__ uint4 g_Wfc[(size_t)OUTSZ * HID / 4];           // W_fc split

// ---------------------------------------------------------------------------
// Helpers
// ---------------------------------------------------------------------------
__device__ __forceinline__ void ffma2(float2& d, const float2& a, const float2& b)
{
    asm("fma.rn.f32x2 %0, %1, %2, %0;"
        : "+l"(reinterpret_cast<unsigned long long&>(d))
        : "l"(reinterpret_cast<const unsigned long long&>(a)),
          "l"(reinterpret_cast<const unsigned long long&>(b)));
}

__device__ __forceinline__ uint2 split_h2(float x, float y)
{
    __half2 hi = __floats2half2_rn(x, y);
    float2 hf = __half22float2(hi);
    __half2 lo = __floats2half2_rn(x - hf.x, y - hf.y);
    uint2 r;
    r.x = *(uint32_t*)&hi;
    r.y = *(uint32_t*)&lo;
    return r;
}

__device__ __forceinline__ void mbar_init(uint32_t addr, uint32_t count)
{
    asm volatile("mbarrier.init.shared.b64 [%0], %1;" :: "r"(addr), "r"(count)
                 : "memory");
}
__device__ __forceinline__ void mbar_expect_tx(uint32_t addr, uint32_t bytes)
{
    asm volatile("mbarrier.arrive.expect_tx.shared.b64 _, [%0], %1;"
                 :: "r"(addr), "r"(bytes) : "memory");
}
__device__ __forceinline__ void mbar_wait(uint32_t addr, uint32_t parity)
{
    asm volatile(
        "{\n\t"
        ".reg .pred P;\n\t"
        "LW%=:\n\t"
        "mbarrier.try_wait.parity.acquire.cta.shared::cta.b64 P, [%0], %1;\n\t"
        "@P bra LD%=;\n\t"
        "bra LW%=;\n\t"
        "LD%=:\n\t"
        "}"
        :: "r"(addr), "r"(parity) : "memory");
}

__device__ __forceinline__ void cp16(uint32_t dst, const void* src)
{
    asm volatile("cp.async.cg.shared.global [%0], [%1], 16;"
                 :: "r"(dst), "l"(src) : "memory");
}
__device__ __forceinline__ void cp_commit()
{
    asm volatile("cp.async.commit_group;" ::: "memory");
}

// ---------------------------------------------------------------------------
// Pre-split: fp32 -> (hi fp16, lo fp16) packed as uint2 per fp32-pair.
// ---------------------------------------------------------------------------
__global__ void presplit(const float4* __restrict__ in, uint4* __restrict__ out,
                         int n4)
{
    for (int i = blockIdx.x * blockDim.x + threadIdx.x; i < n4;
         i += gridDim.x * blockDim.x) {
        float4 v = in[i];
        uint2 a = split_h2(v.x, v.y);
        uint2 b = split_h2(v.z, v.w);
        out[i] = make_uint4(a.x, a.y, b.x, b.y);
    }
}

// ---------------------------------------------------------------------------
// 3-term fp16 split GEMM (NT), PRE-SPLIT operands, 2-stage cp.async pipeline:
// C[m,n] = sum_k A[m,k]*B[n,k] + bias1[n] (+bias2).
// A,B given as uint2 streams: kpair -> (hi half2, lo half2).
// BM=BN=128, BK=16 (8 kpairs), 256 threads, warp tile 64x32,
// mma.sync.m16n8k16.f16 fp32-accum; AhBh + AhBl + AlBh.
// Stage kb+2's LDGSTS issued right after stage kb's MMAs -> global-load
// latency hidden behind two full MMA phases.
// ---------------------------------------------------------------------------
#define MMA_F16(d, a0, a1, a2, a3, b0, b1)                                    \
    asm("mma.sync.aligned.m16n8k16.row.col.f32.f16.f16.f32 "                   \
        "{%0,%1,%2,%3},{%4,%5,%6,%7},{%8,%9},{%0,%1,%2,%3};"                   \
        : "+f"((d)[0]), "+f"((d)[1]), "+f"((d)[2]), "+f"((d)[3])               \
        : "r"(a0), "r"(a1), "r"(a2), "r"(a3), "r"(b0), "r"(b1))

#define HPAD 10   // uint2 row stride (8 kpairs + 2 pad)

__global__ void __launch_bounds__(256, 2)
hgemm_pre(const uint2* __restrict__ Ah, const uint2* __restrict__ Bh,
          const float* __restrict__ bias1, const float* __restrict__ bias2,
          float* __restrict__ C, int K2, int N)
{
    __shared__ uint2 As[2][128][HPAD];
    __shared__ uint2 Bs[2][128][HPAD];

    const int tid  = threadIdx.x;
    const int lane = tid & 31;
    const int warp = tid >> 5;
    const int wm = warp & 1;
    const int wn = warp >> 1;
    const int g  = lane >> 2;
    const int t  = lane & 3;

    const size_t m0 = (size_t)blockIdx.x * 128;
    const int    n0 = blockIdx.y * 128;

    // Load mapping: 2 threads per row; each thread covers 4 kpairs (2x16B).
    const int frow = tid >> 1;
    const int fc2  = (tid & 1) * 4;     // kpair offset 0 or 4
    const uint2* Ag = Ah + (m0 + frow) * (size_t)K2 + fc2;
    const uint2* Bg = Bh + (size_t)(n0 + frow) * K2 + fc2;

    const uint32_t sA0 = (uint32_t)__cvta_generic_to_shared(&As[0][frow][fc2]);
    const uint32_t sA1 = (uint32_t)__cvta_generic_to_shared(&As[1][frow][fc2]);
    const uint32_t sB0 = (uint32_t)__cvta_generic_to_shared(&Bs[0][frow][fc2]);
    const uint32_t sB1 = (uint32_t)__cvta_generic_to_shared(&Bs[1][frow][fc2]);

    const int nblk = K2 >> 3;           // 8 kpairs per block

    // Prime stages 0 and 1.
    cp16(sA0, Ag);          cp16(sA0 + 16, Ag + 2);
    cp16(sB0, Bg);          cp16(sB0 + 16, Bg + 2);
    cp_commit();
    cp16(sA1, Ag + 8);      cp16(sA1 + 16, Ag + 10);
    cp16(sB1, Bg + 8);      cp16(sB1 + 16, Bg + 10);
    cp_commit();

    float acc[4][4][4];
#pragma unroll
    for (int i = 0; i < 4; ++i)
#pragma unroll
        for (int j = 0; j < 4; ++j)
#pragma unroll
            for (int q = 0; q < 4; ++q) acc[i][j][q] = 0.f;

    for (int kb = 0; kb < nblk; ++kb) {
        if (kb == nblk - 1)
            asm volatile("cp.async.wait_group 0;" ::: "memory");
        else
            asm volatile("cp.async.wait_group 1;" ::: "memory");
        __syncthreads();

        const int s = kb & 1;
        uint32_t ah[4][4], al[4][4], bh[4][2], bl[4][2];
#pragma unroll
        for (int i = 0; i < 4; ++i) {
            const int row = wm * 64 + i * 16 + g;
            uint2 q00 = As[s][row][t];
            uint2 q10 = As[s][row + 8][t];
            uint2 q01 = As[s][row][t + 4];
            uint2 q11 = As[s][row + 8][t + 4];
            ah[i][0] = q00.x; ah[i][1] = q10.x; ah[i][2] = q01.x; ah[i][3] = q11.x;
            al[i][0] = q00.y; al[i][1] = q10.y; al[i][2] = q01.y; al[i][3] = q11.y;
        }
#pragma unroll
        for (int j = 0; j < 4; ++j) {
            const int n = wn * 32 + j * 8 + g;
            uint2 p0 = Bs[s][n][t];
            uint2 p1 = Bs[s][n][t + 4];
            bh[j][0] = p0.x; bh[j][1] = p1.x;
            bl[j][0] = p0.y; bl[j][1] = p1.y;
        }
#pragma unroll
        for (int i = 0; i < 4; ++i)
#pragma unroll
            for (int j = 0; j < 4; ++j) {
                MMA_F16(acc[i][j], ah[i][0], ah[i][1], ah[i][2], ah[i][3],
                        bh[j][0], bh[j][1]);
                MMA_F16(acc[i][j], ah[i][0], ah[i][1], ah[i][2], ah[i][3],
                        bl[j][0], bl[j][1]);
                MMA_F16(acc[i][j], al[i][0], al[i][1], al[i][2], al[i][3],
                        bh[j][0], bh[j][1]);
            }
        __syncthreads();

        // Issue stage kb+2 into the buffer we just finished reading.
        if (kb + 2 < nblk) {
            const int koff = (kb + 2) * 8;
            const uint32_t dA = s ? sA0 : sA1;   // buffer (kb+2)&1 == kb&1
            const uint32_t dB = s ? sB0 : sB1;
            // note: (kb+2)&1 == kb&1 == s -> write buffer s
            cp16(s ? sA1 : sA0, Ag + koff);      // correct buffer = s
            cp16((s ? sA1 : sA0) + 16, Ag + koff + 2);
            cp16(s ? sB1 : sB0, Bg + koff);
            cp16((s ? sB1 : sB0) + 16, Bg + koff + 2);
            cp_commit();
            (void)dA; (void)dB;
        }
    }

#pragma unroll
    for (int j = 0; j < 4; ++j) {
        int col = n0 + wn * 32 + j * 8 + 2 * t;
        float b0 = bias1[col], b1 = bias1[col + 1];
        if (bias2) { b0 += bias2[col]; b1 += bias2[col + 1]; }
#pragma unroll
        for (int i = 0; i < 4; ++i) {
            size_t row = m0 + wm * 64 + i * 16 + g;
            *(float2*)(C + row * N + col) =
                make_float2(acc[i][j][0] + b0, acc[i][j][1] + b1);
            *(float2*)(C + (row + 8) * N + col) =
                make_float2(acc[i][j][2] + b0, acc[i][j][3] + b1);
        }
    }
}

// ---------------------------------------------------------------------------
// LSTM recurrence v6 (R10, FROZEN): two-group software pipeline,
// per-(g,slot,rank) mbarriers + st.async scatter; hs emitted pre-split.
// ---------------------------------------------------------------------------
__global__ void __launch_bounds__(256, 1)
lstm_rec_kernel(const float* __restrict__ Whh,
                const float* __restrict__ Xp,
                uint2* __restrict__ hs_h)
{
    __shared__ float  hsm[2][3][8][64];        // [g][slot][rank][bb*32+jj]
    __shared__ float4 part[2][8][2][32];       // [g][warp][bb][jj] = 4 gates
    __shared__ __align__(8) unsigned long long mbar[48];  // [g][slot][rank]

    const int tid  = threadIdx.x;
    const int lane = tid & 31;
    const int w    = tid >> 5;

    unsigned r;
    asm("mov.u32 %0, %%cluster_ctarank;" : "=r"(r));
    const int cl = blockIdx.x >> 3;

    const uint32_t hsm_s = (uint32_t)__cvta_generic_to_shared(hsm);
    const uint32_t mb_s  = (uint32_t)__cvta_generic_to_shared(mbar);

    uint32_t pd[8], pm[8];
#pragma unroll
    for (int dst = 0; dst < 8; ++dst) {
        asm("mapa.shared::cluster.u32 %0, %1, %2;"
            : "=r"(pd[dst]) : "r"(hsm_s), "r"(dst));
        asm("mapa.shared::cluster.u32 %0, %1, %2;"
            : "=r"(pm[dst]) : "r"(mb_s), "r"(dst));
    }

    float2 wreg[4][16];
#pragma unroll
    for (int rr = 0; rr < 4; ++rr) {
        int grow = rr * 256 + (int)r * 32 + lane;
        const float2* wp = (const float2*)(Whh + (size_t)grow * 256 + w * 32);
#pragma unroll
        for (int k2 = 0; k2 < 16; ++k2) wreg[rr][k2] = wp[k2];
    }
    for (int i = tid; i < 2 * 3 * 8 * 64; i += 256) ((float*)hsm)[i] = 0.f;
    if (tid < 48) mbar_init(mb_s + tid * 8, 1);
    __syncthreads();
    if (tid < 48) mbar_expect_tx(mb_s + tid * 8, 256u);
    asm volatile("barrier.cluster.arrive.aligned;" ::: "memory");
    asm volatile("barrier.cluster.wait.aligned;"   ::: "memory");

    const int mg = tid >> 6;
    const int tl = tid & 63;
    const int bb = tl >> 5;
    const int jj = tl & 31;
    float c = 0.f;
    int par = 0;
    int rs = 0;

    const float* xp_base = Xp + ((size_t)cl * 4 + mg * 2 + bb) * 1024
                              + (int)r * 32 + jj;
    float xc0 = 0.f, xc1 = 0.f, xc2 = 0.f, xc3 = 0.f;
    if (tid < 128) {
        xc0 = xp_base[0]; xc1 = xp_base[256];
        xc2 = xp_base[512]; xc3 = xp_base[768];
    }

    for (int t = 0; t < T_STEPS; ++t) {
        const int ws = (rs == 2) ? 0 : rs + 1;

        // ============ group A ============
        if (t > 0)
            mbar_wait(mb_s + ((0 * 3 + rs) * 8 + w) * 8, (par >> rs) & 1);

        float xn0 = 0.f, xn1 = 0.f, xn2 = 0.f, xn3 = 0.f;
        if (tid < 128 && t + 1 < T_STEPS) {
            const float* xp = xp_base + (size_t)(t + 1) * 64 * 1024;
            xn0 = xp[0]; xn1 = xp[256]; xn2 = xp[512]; xn3 = xp[768];
        }

        {
            float2 acc[4][2];
#pragma unroll
            for (int rr = 0; rr < 4; ++rr) {
                acc[rr][0] = make_float2(0.f, 0.f);
                acc[rr][1] = make_float2(0.f, 0.f);
            }
            const float* hb = &hsm[0][rs][w][0];
#pragma unroll
            for (int k2 = 0; k2 < 16; ++k2) {
                float2 h0 = *(const float2*)(hb + 2 * k2);
                float2 h1 = *(const float2*)(hb + 32 + 2 * k2);
#pragma unroll
                for (int rr = 0; rr < 4; ++rr) {
                    ffma2(acc[rr][0], wreg[rr][k2], h0);
                    ffma2(acc[rr][1], wreg[rr][k2], h1);
                }
            }
#pragma unroll
            for (int b = 0; b < 2; ++b)
                part[0][w][b][lane] = make_float4(acc[0][b].x + acc[0][b].y,
                                                  acc[1][b].x + acc[1][b].y,
                                                  acc[2][b].x + acc[2][b].y,
                                                  acc[3][b].x + acc[3][b].y);
        }
        __syncthreads();
        if (t > 0 && tid < 8)
            mbar_expect_tx(mb_s + ((0 * 3 + rs) * 8 + tid) * 8, 256u);

        if (tid < 64) {
            float s0 = xc0, s1 = xc1, s2 = xc2, s3 = xc3;
#pragma unroll
            for (int w8 = 0; w8 < 8; ++w8) {
                float4 p = part[0][w8][bb][jj];
                s0 += p.x; s1 += p.y; s2 += p.z; s3 += p.w;
            }
            float ig = __fdividef(1.f, 1.f + __expf(-s0));
            float fg = __fdividef(1.f, 1.f + __expf(-s1));
            float e2 = __expf(2.f * s2);
            float gg = __fdividef(e2 - 1.f, e2 + 1.f);
            float og = __fdividef(1.f, 1.f + __expf(-s3));
            c = fg * c + ig * gg;
            float ec = __expf(2.f * c);
            float h = og * __fdividef(ec - 1.f, ec + 1.f);

            if (t < T_STEPS - 1) {
                uint32_t hv = __float_as_uint(h);
                uint32_t doff = (uint32_t)(0 * 6144 + ws * 2048 + (int)r * 256
                                           + tl * 4);
                uint32_t moff = (uint32_t)(((0 * 3 + ws) * 8 + (int)r) * 8);
#pragma unroll
                for (int dst = 0; dst < 8; ++dst)
                    asm volatile(
                        "st.async.shared::cluster.mbarrier::complete_tx::bytes"
                        ".u32 [%0], %1, [%2];"
                        :: "r"(pd[dst] + doff), "r"(hv), "r"(pm[dst] + moff)
                        : "memory");
            }
            float hn = __shfl_down_sync(0xFFFFFFFFu, h, 1);
            if (!(jj & 1)) {
                uint2 sv = split_h2(h, hn);
                hs_h[((size_t)t * 64 + cl * 4 + bb) * 128
                     + (int)r * 16 + (jj >> 1)] = sv;
            }
        }

        // ============ group B ============
        if (t > 0)
            mbar_wait(mb_s + ((1 * 3 + rs) * 8 + w) * 8, (par >> rs) & 1);

        {
            float2 acc[4][2];
#pragma unroll
            for (int rr = 0; rr < 4; ++rr) {
                acc[rr][0] = make_float2(0.f, 0.f);
                acc[rr][1] = make_float2(0.f, 0.f);
            }
            const float* hb = &hsm[1][rs][w][0];
#pragma unroll
            for (int k2 = 0; k2 < 16; ++k2) {
                float2 h0 = *(const float2*)(hb + 2 * k2);
                float2 h1 = *(const float2*)(hb + 32 + 2 * k2);
#pragma unroll
                for (int rr = 0; rr < 4; ++rr) {
                    ffma2(acc[rr][0], wreg[rr][k2], h0);
                    ffma2(acc[rr][1], wreg[rr][k2], h1);
                }
            }
#pragma unroll
            for (int b = 0; b < 2; ++b)
                part[1][w][b][lane] = make_float4(acc[0][b].x + acc[0][b].y,
                                                  acc[1][b].x + acc[1][b].y,
                                                  acc[2][b].x + acc[2][b].y,
                                                  acc[3][b].x + acc[3][b].y);
        }
        __syncthreads();
        if (t > 0 && tid < 8)
            mbar_expect_tx(mb_s + ((1 * 3 + rs) * 8 + tid) * 8, 256u);

        if (tid >= 64 && tid < 128) {
            float s0 = xc0, s1 = xc1, s2 = xc2, s3 = xc3;
#pragma unroll
            for (int w8 = 0; w8 < 8; ++w8) {
                float4 p = part[1][w8][bb][jj];
                s0 += p.x; s1 += p.y; s2 += p.z; s3 += p.w;
            }
            float ig = __fdividef(1.f, 1.f + __expf(-s0));
            float fg = __fdividef(1.f, 1.f + __expf(-s1));
            float e2 = __expf(2.f * s2);
            float gg = __fdividef(e2 - 1.f, e2 + 1.f);
            float og = __fdividef(1.f, 1.f + __expf(-s3));
            c = fg * c + ig * gg;
            float ec = __expf(2.f * c);
            float h = og * __fdividef(ec - 1.f, ec + 1.f);

            if (t < T_STEPS - 1) {
                uint32_t hv = __float_as_uint(h);
                uint32_t doff = (uint32_t)(1 * 6144 + ws * 2048 + (int)r * 256
                                           + tl * 4);
                uint32_t moff = (uint32_t)(((1 * 3 + ws) * 8 + (int)r) * 8);
#pragma unroll
                for (int dst = 0; dst < 8; ++dst)
                    asm volatile(
                        "st.async.shared::cluster.mbarrier::complete_tx::bytes"
                        ".u32 [%0], %1, [%2];"
                        :: "r"(pd[dst] + doff), "r"(hv), "r"(pm[dst] + moff)
                        : "memory");
            }
            float hn = __shfl_down_sync(0xFFFFFFFFu, h, 1);
            if (!(jj & 1)) {
                uint2 sv = split_h2(h, hn);
                hs_h[((size_t)t * 64 + cl * 4 + 2 + bb) * 128
                     + (int)r * 16 + (jj >> 1)] = sv;
            }
        }

        xc0 = xn0; xc1 = xn1; xc2 = xn2; xc3 = xn3;
        if (t > 0) par ^= (1 << rs);
        rs = ws;
    }

    asm volatile("barrier.cluster.arrive.aligned;" ::: "memory");
    asm volatile("barrier.cluster.wait.aligned;"   ::: "memory");
}

// ---------------------------------------------------------------------------
// Launch
// ---------------------------------------------------------------------------
extern "C" void kernel_launch(void* const* d_in, const int* in_sizes, int n_in,
                              void* d_out, int out_size)
{
    const float* inputs = (const float*)d_in[0];
    const float* W_ih   = (const float*)d_in[1];
    const float* W_hh   = (const float*)d_in[2];
    const float* b_ih   = (const float*)d_in[3];
    const float* b_hh   = (const float*)d_in[4];
    const float* W_fc   = (const float*)d_in[5];
    const float* b_fc   = (const float*)d_in[6];
    float* out = (float*)d_out;

    float *Xp;
    uint4 *Ah, *Wih, *hsh, *Wfc;
    cudaGetSymbolAddress((void**)&Xp,  g_Xp);
    cudaGetSymbolAddress((void**)&Ah,  g_Ah);
    cudaGetSymbolAddress((void**)&Wih, g_Wih);
    cudaGetSymbolAddress((void**)&hsh, g_hsh);
    cudaGetSymbolAddress((void**)&Wfc, g_Wfc);

    // 0) Pre-split fp32 -> fp16 hi/lo pairs.
    presplit<<<4096, 256>>>((const float4*)inputs, Ah, MROWS * INSZ / 4);
    presplit<<<512, 256>>>((const float4*)W_ih, Wih, G4 * INSZ / 4);
    presplit<<<32, 256>>>((const float4*)W_fc, Wfc, OUTSZ * HID / 4);

    // 1) Xp = inputs @ W_ih^T + (b_ih + b_hh)   [131072 x 1024]
    {
        dim3 grid(MROWS / 128, G4 / 128);
        hgemm_pre<<<grid, 256>>>((const uint2*)Ah, (const uint2*)Wih,
                                 b_ih, b_hh, Xp, INSZ / 2, G4);
    }

    // 2) LSTM recurrence -> hs (pre-split) [131072 x 256]
    {
        cudaLaunchConfig_t cfg = {};
        cfg.gridDim = dim3(128, 1, 1);
        cfg.blockDim = dim3(256, 1, 1);
        cfg.dynamicSmemBytes = 0;
        cfg.stream = 0;
        cudaLaunchAttribute attr[1];
        attr[0].id = cudaLaunchAttributeClusterDimension;
        attr[0].val.clusterDim.x = 8;
        attr[0].val.clusterDim.y = 1;
        attr[0].val.clusterDim.z = 1;
        cfg.attrs = attr;
        cfg.numAttrs = 1;
        cudaLaunchKernelEx(&cfg, lstm_rec_kernel, W_hh, (const float*)Xp,
                           (uint2*)hsh);
    }

    // 3) out = hs @ W_fc^T + b_fc   [131072 x 128]
    {
        dim3 grid(MROWS / 128, OUTSZ / 128);
        hgemm_pre<<<grid, 256>>>((const uint2*)hsh, (const uint2*)Wfc,
                                 b_fc, (const float*)nullptr, out,
                                 HID / 2, OUTSZ);
    }
}